// round 16
// baseline (speedup 1.0000x reference)
#include <cuda_runtime.h>
#include <cstdint>

#define TU      204800     // 400 * 512 upsampled length
#define TBLK    400        // frames
#define BATCH   16
#define NH      9          // harmonic_num + 1
#define NROW1   12800      // TU / 16
#define SPT     4          // samples per thread (quarter of a radix-16 row)

// Transposed padded level-1 prefix: [b][R(0..NROW1)][12]; [b][0][h]=0, [b][R][h]=P[R-1].
// 48B row stride keeps float4 alignment; cols 9..11 are pad.
__device__ float g_P2T[BATCH * (NROW1 + 1) * 12];      // 9.8 MB
// Transposed chain checkpoints: [b][t*4+qi][12]; qi=0 -> 0, qi=1..3 -> s4,s8,s12.
__device__ float g_seq4T[BATCH * TBLK * 4 * 12];       // 1.2 MB
// Runtime-opaque 1: forces mad.lo -> IMAD (fma pipe) for threefry adds.
__device__ uint32_t g_one = 1;

__device__ __forceinline__ uint32_t madd(uint32_t a, uint32_t b, uint32_t c) {
    uint32_t d;
    asm("mad.lo.s32 %0, %1, %2, %3;" : "=r"(d) : "r"(a), "r"(b), "r"(c));
    return d;
}

// ---------------- threefry2x32, key=(0,42), counter (0, nbase+off); bits = x0^x1 ----------------
// off is compile-time; entry add nbase+off+42 fused into one IMAD.
__device__ __forceinline__ uint32_t noise_bits(uint32_t nbase, uint32_t off42, uint32_t one) {
    const uint32_t kK  = 0x1BD11BDAu ^ 42u;
    uint32_t x1 = madd(one, off42, nbase);              // nbase + off + 42, IMAD
    uint32_t x0 = x1;                                   // round 1: x0 was 0
    x1 = __funnelshift_l(x1, x1, 13) ^ x0;
#define TFR(r) { x0 = madd(x1, one, x0); x1 = __funnelshift_l(x1, x1, (r)); x1 ^= x0; }
    TFR(15) TFR(26) TFR(6)
    x0 = madd(one, 42u, x0);      x1 = madd(one, kK + 1u, x1);
    TFR(17) TFR(29) TFR(16) TFR(24)
    x0 = madd(one, kK, x0);       x1 = madd(one, 2u, x1);
    TFR(13) TFR(15) TFR(26) TFR(6)
    /* +ks0 = 0 */                x1 = madd(one, 45u, x1);
    TFR(17) TFR(29) TFR(16) TFR(24)
    x0 = madd(one, 42u, x0);      x1 = madd(one, kK + 4u, x1);
    TFR(13) TFR(15) TFR(26) TFR(6)
    x0 = madd(one, kK, x0);       x1 = madd(one, 5u, x1);
#undef TFR
    return x0 ^ x1;
}

// ---------------- MUFU helpers ----------------
__device__ __forceinline__ float mufu_sin(float r)  { float v; asm("sin.approx.f32 %0, %1;"  : "=f"(v) : "f"(r)); return v; }
__device__ __forceinline__ float mufu_lg2(float t)  { float v; asm("lg2.approx.f32 %0, %1;"  : "=f"(v) : "f"(t)); return v; }
__device__ __forceinline__ float mufu_ex2(float t)  { float v; asm("ex2.approx.f32 %0, %1;"  : "=f"(v) : "f"(t)); return v; }
__device__ __forceinline__ float mufu_rcp(float t)  { float v; asm("rcp.approx.f32 %0, %1;"  : "=f"(v) : "f"(t)); return v; }
__device__ __forceinline__ float mufu_sqrt(float t) { float v; asm("sqrt.approx.f32 %0, %1;" : "=f"(v) : "f"(t)); return v; }

// ---------------- normal/sqrt(2) = erfinv(u) = p*u; truncated Giles, branchless tail ----------------
// u2 = (bits>>9)|0x40000000 in ONE SHF: funnelshift_r(bits, 0x80, 9) = (bits>>9)|(0x80<<23).
// Two-add u form REQUIRED: lo = nextafter(-1,0) guards u > -1 strictly.
__device__ __forceinline__ float normal_pu(uint32_t bits) {
    float u2 = __uint_as_float(__funnelshift_r(bits, 0x80u, 9));   // 2*u01 + 2, exact
    const float lo = -0.99999994039535522461f;                      // nextafter(-1,0)
    float u = __fadd_rn(__fadd_rn(u2, -2.0f), lo);                  // fl(2*u01 + lo) > -1
    float t = fmaf(-u, u, 1.0f);                                    // 1-u^2 > 0
    float w = __fmul_rn(mufu_lg2(t), -0.6931471805599453f);         // -ln(1-u^2)
    float wc = w - 2.5f;
    float p = -4.39150654e-06f;
    p = fmaf(p, wc, 0.00021858087f);
    p = fmaf(p, wc, -0.00125372503f);
    p = fmaf(p, wc, -0.00417768164f);
    p = fmaf(p, wc, 0.246640727f);
    p = fmaf(p, wc, 1.50140941f);
    float st = mufu_sqrt(w) - 3.0f;
    float pt = fmaf(fmaf(0.00943887047f, st, 1.00167406f), st, 2.83297682f);
    p = (w < 5.0f) ? p : pt;
    return __fmul_rn(p, u);
}

// ---------------- sin(phase): mod-2pi reduction, zero alu ops ----------------
__device__ __forceinline__ float sin_phase(float phase) {
    const float MAGIC = 12582912.0f;                   // 1.5 * 2^23
    const float INV2PI = 0.15915494309189535f;
    const float P1 = 6.28125f;                         // 2pi head, 9 mantissa bits
    const float P2 = 1.9353071795864769e-3f;           // 2pi - P1
    float tmp = fmaf(phase, INV2PI, MAGIC);
    float fk = tmp - MAGIC;                            // exact round-to-nearest integer
    float r = fmaf(fk, -P1, phase);                    // exact
    r = fmaf(fk, -P2, r);                              // one rounding
    return mufu_sin(r);
}

// ---------------- fast tanh ----------------
__device__ __forceinline__ float tanh_fast(float z) {
    float a = fminf(fabsf(z) * 2.8853900817779268f, 64.0f);
    float e = mufu_ex2(a);
    float th = __fmul_rn(e - 1.0f, mufu_rcp(e + 1.0f));
    return copysignf(th, z);
}

// ---------------- Kernel 1: XLA ReduceWindowRewriter radix-16 scan -> g_P2T, g_seq4T ----------------
__global__ void scan16_kernel(const float* __restrict__ f0) {
    __shared__ float sm16[TBLK];
    __shared__ float U[TBLK];
    __shared__ float smT1[TBLK * 16];
    __shared__ float inner3[800];
    __shared__ float O2s[800];
    __shared__ float T3[50];
    __shared__ float O3s[50];
    __shared__ float inner4[50];

    const int row = blockIdx.x;                 // 0..143 = b*9+h
    const int b = row / NH, h = row % NH;
    const float m = (float)(h + 1);

    for (int t = threadIdx.x; t < TBLK; t += blockDim.x) {
        float x = __fmul_rn(__fdiv_rn(f0[b * TBLK + t], 48000.0f), m);
        float s = 0.0f;
        g_seq4T[(b * TBLK * 4 + t * 4 + 0) * 12 + h] = 0.0f;
#pragma unroll
        for (int k = 0; k < 16; k++) {
            s = __fadd_rn(s, x);
            if (k == 3)  g_seq4T[(b * TBLK * 4 + t * 4 + 1) * 12 + h] = s;
            if (k == 7)  g_seq4T[(b * TBLK * 4 + t * 4 + 2) * 12 + h] = s;
            if (k == 11) g_seq4T[(b * TBLK * 4 + t * 4 + 3) * 12 + h] = s;
        }
        sm16[t] = s;
    }
    __syncthreads();

    for (int t = threadIdx.x; t < TBLK; t += blockDim.x) {
        float v = sm16[t], s = 0.0f;
#pragma unroll
        for (int k = 0; k < 16; k++) {
            s = __fadd_rn(s, v);
            smT1[t * 16 + k] = s;
        }
        U[t] = s;
    }
    __syncthreads();

    for (int R3 = threadIdx.x; R3 < 50; R3 += blockDim.x) {
        float s = 0.0f;
        for (int j = 0; j < 16; j++) {
            s = __fadd_rn(s, U[(16 * R3 + j) >> 1]);
            inner3[R3 * 16 + j] = s;
        }
        T3[R3] = s;
    }
    __syncthreads();

    if (threadIdx.x == 0) {
        float T4[4], O4[4];
        for (int r = 0; r < 4; r++) {
            float s = 0.0f;
            for (int j = 0; j < 16; j++) {
                int idx = 16 * r + j;
                float v = (idx < 50) ? T3[idx] : 0.0f;
                s = __fadd_rn(s, v);
                if (idx < 50) inner4[idx] = s;
            }
            T4[r] = s;
        }
        float s = 0.0f;
        for (int r = 0; r < 4; r++) { s = __fadd_rn(s, T4[r]); O4[r] = s; }
        for (int i = 0; i < 50; i++) {
            float e = ((i >> 4) == 0) ? 0.0f : O4[(i >> 4) - 1];
            O3s[i] = __fadd_rn(inner4[i], e);
        }
    }
    __syncthreads();

    for (int i2 = threadIdx.x; i2 < 800; i2 += blockDim.x) {
        float e = ((i2 >> 4) == 0) ? 0.0f : O3s[(i2 >> 4) - 1];
        O2s[i2] = __fadd_rn(inner3[i2], e);
    }
    __syncthreads();

    if (threadIdx.x == 0) g_P2T[(b * (NROW1 + 1)) * 12 + h] = 0.0f;
    for (int R = threadIdx.x; R < NROW1; R += blockDim.x) {
        int t = R >> 5, k = R & 15, R2 = R >> 4;
        float e = (R2 == 0) ? 0.0f : O2s[R2 - 1];
        g_P2T[(b * (NROW1 + 1) + R + 1) * 12 + h] = __fadd_rn(smT1[t * 16 + k], e);
    }
}

// ---------------- Kernel 2: one thread = 4 samples (quarter radix-16 row) ----------------
__global__ void __launch_bounds__(256) nsf_kernel(const float* __restrict__ f0,
                                                  const float* __restrict__ W,
                                                  const float* __restrict__ bias,
                                                  float* __restrict__ out) {
    const int T = blockIdx.x * blockDim.x + threadIdx.x;   // 0 .. BATCH*TU/4-1
    const int b = T / (TU / SPT);
    const int q = T - b * (TU / SPT);                      // quarter-row index in batch
    const int R = q >> 2;                                  // radix-16 row
    const int qi = q & 3;                                  // which quarter
    const int t = R >> 5;
    const int s0 = q << 2;                                 // first sample in batch row

    const uint32_t one = g_one;
    const uint32_t nbase = (uint32_t)(b * TU + s0) * (uint32_t)NH;

    const float f0t = __ldg(&f0[b * TBLK + t]);
    const float rad = __fdiv_rn(f0t, 48000.0f);
    const bool voiced = (f0t > 1.0f);
    const float bias0 = __ldg(&bias[0]);
    const float namp2 = voiced ? 0.0042426406871192851f   // 0.003  * sqrt(2)
                               : 0.047140452079103173f;   // 0.1/3  * sqrt(2)
    const float samp  = voiced ? 0.1f : 0.0f;

    // Vectorized table loads: 48B-aligned 12-float rows.
    float pre[NH], seqv[NH], xh[NH], wv[NH];
    {
        const float4* pb = reinterpret_cast<const float4*>(&g_P2T[(b * (NROW1 + 1) + R) * 12]);
        float4 p0 = pb[0], p1 = pb[1];
        float  p8 = reinterpret_cast<const float*>(pb)[8];
        pre[0]=p0.x; pre[1]=p0.y; pre[2]=p0.z; pre[3]=p0.w;
        pre[4]=p1.x; pre[5]=p1.y; pre[6]=p1.z; pre[7]=p1.w; pre[8]=p8;

        const float4* sb = reinterpret_cast<const float4*>(&g_seq4T[(b * TBLK * 4 + (t << 2) + qi) * 12]);
        float4 s0v = sb[0], s1v = sb[1];
        float  s8 = reinterpret_cast<const float*>(sb)[8];
        seqv[0]=s0v.x; seqv[1]=s0v.y; seqv[2]=s0v.z; seqv[3]=s0v.w;
        seqv[4]=s1v.x; seqv[5]=s1v.y; seqv[6]=s1v.z; seqv[7]=s1v.w; seqv[8]=s8;
    }
#pragma unroll
    for (int h = 0; h < NH; h++) {
        xh[h] = __fmul_rn(rad, (float)(h + 1));           // fl(rad*m): matches scan16
        wv[h] = __ldg(&W[h]);
    }

    float4 o;
    float* ov = &o.x;
#pragma unroll
    for (int i = 0; i < SPT; i++) {
        float accS = 0.0f, accN = 0.0f;
#pragma unroll
        for (int h = 0; h < NH; h++) {
            seqv[h] = __fadd_rn(seqv[h], xh[h]);          // continue exact window chain
            const float C = __fadd_rn(seqv[h], pre[h]);
            const float phase = __fmul_rn(C, 6.283185307179586f);
            const float sv = sin_phase(phase);
            const uint32_t bits = noise_bits(nbase, (uint32_t)(i * NH + h) + 42u, one);
            const float pu = normal_pu(bits);
            accS = fmaf(sv, wv[h], accS);
            accN = fmaf(pu, wv[h], accN);
        }
        float z = fmaf(accN, namp2, bias0);
        z = fmaf(accS, samp, z);
        ov[i] = tanh_fast(z);
    }
    reinterpret_cast<float4*>(out)[T] = o;                 // coalesced 16B store
}

extern "C" void kernel_launch(void* const* d_in, const int* in_sizes, int n_in,
                              void* d_out, int out_size) {
    const float* f0 = (const float*)d_in[0];
    const float* W;
    const float* bias;
    if (n_in >= 4 && in_sizes[2] == NH)      { W = (const float*)d_in[2]; bias = (const float*)d_in[3]; }
    else if (n_in >= 3 && in_sizes[1] == NH) { W = (const float*)d_in[1]; bias = (const float*)d_in[2]; }
    else                                     { W = (const float*)d_in[2]; bias = (const float*)d_in[3]; }
    float* out = (float*)d_out;

    scan16_kernel<<<BATCH * NH, 256>>>(f0);
    const int nthreads = BATCH * TU / SPT;                 // 819200
    nsf_kernel<<<nthreads / 256, 256>>>(f0, W, bias, out);
}

// round 17
// speedup vs baseline: 1.0524x; 1.0524x over previous
#include <cuda_runtime.h>
#include <cstdint>

#define TU      204800     // 400 * 512 upsampled length
#define TBLK    400        // frames
#define BATCH   16
#define NH      9          // harmonic_num + 1
#define NROW1   12800      // TU / 16
#define SPT     2          // samples per thread (eighth of a radix-16 row)

// Padded level-1 prefix: [row][0..NROW1], entry 0 = 0, entry R = P[R-1].
__device__ float g_P2[BATCH * NH * (NROW1 + 1)];       // 7.4 MB
// Chain checkpoints: [row][t][j], j=0..7 -> s_{2j} (s0 = 0). 32B-aligned rows.
__device__ float g_seq8[BATCH * NH * TBLK * 8];        // 1.8 MB
// Runtime-opaque 1: forces mad.lo -> IMAD (fma pipe) for threefry adds.
__device__ uint32_t g_one = 1;

__device__ __forceinline__ uint32_t madd(uint32_t a, uint32_t b, uint32_t c) {
    uint32_t d;
    asm("mad.lo.s32 %0, %1, %2, %3;" : "=r"(d) : "r"(a), "r"(b), "r"(c));
    return d;
}

// ---------------- threefry2x32, key=(0,42), counter (0, nbase+off); bits = x0^x1 ----------------
__device__ __forceinline__ uint32_t noise_bits(uint32_t nbase, uint32_t off42, uint32_t one) {
    const uint32_t kK  = 0x1BD11BDAu ^ 42u;
    uint32_t x1 = madd(one, off42, nbase);              // nbase + off + 42, one IMAD
    uint32_t x0 = x1;                                   // round 1: x0 was 0
    x1 = __funnelshift_l(x1, x1, 13) ^ x0;
#define TFR(r) { x0 = madd(x1, one, x0); x1 = __funnelshift_l(x1, x1, (r)); x1 ^= x0; }
    TFR(15) TFR(26) TFR(6)
    x0 = madd(one, 42u, x0);      x1 = madd(one, kK + 1u, x1);
    TFR(17) TFR(29) TFR(16) TFR(24)
    x0 = madd(one, kK, x0);       x1 = madd(one, 2u, x1);
    TFR(13) TFR(15) TFR(26) TFR(6)
    /* +ks0 = 0 */                x1 = madd(one, 45u, x1);
    TFR(17) TFR(29) TFR(16) TFR(24)
    x0 = madd(one, 42u, x0);      x1 = madd(one, kK + 4u, x1);
    TFR(13) TFR(15) TFR(26) TFR(6)
    x0 = madd(one, kK, x0);       x1 = madd(one, 5u, x1);
#undef TFR
    return x0 ^ x1;
}

// ---------------- MUFU helpers ----------------
__device__ __forceinline__ float mufu_sin(float r)  { float v; asm("sin.approx.f32 %0, %1;"  : "=f"(v) : "f"(r)); return v; }
__device__ __forceinline__ float mufu_lg2(float t)  { float v; asm("lg2.approx.f32 %0, %1;"  : "=f"(v) : "f"(t)); return v; }
__device__ __forceinline__ float mufu_ex2(float t)  { float v; asm("ex2.approx.f32 %0, %1;"  : "=f"(v) : "f"(t)); return v; }
__device__ __forceinline__ float mufu_rcp(float t)  { float v; asm("rcp.approx.f32 %0, %1;"  : "=f"(v) : "f"(t)); return v; }
__device__ __forceinline__ float mufu_sqrt(float t) { float v; asm("sqrt.approx.f32 %0, %1;" : "=f"(v) : "f"(t)); return v; }

// ---------------- normal/sqrt(2) = erfinv(u) = p*u; truncated Giles, branchless tail ----------------
// u2 = (bits>>9)|0x40000000 in ONE SHF. Two-add u form REQUIRED (u > -1 strictly).
__device__ __forceinline__ float normal_pu(uint32_t bits) {
    float u2 = __uint_as_float(__funnelshift_r(bits, 0x80u, 9));   // 2*u01 + 2, exact
    const float lo = -0.99999994039535522461f;                      // nextafter(-1,0)
    float u = __fadd_rn(__fadd_rn(u2, -2.0f), lo);                  // fl(2*u01 + lo) > -1
    float t = fmaf(-u, u, 1.0f);                                    // 1-u^2 > 0
    float w = __fmul_rn(mufu_lg2(t), -0.6931471805599453f);         // -ln(1-u^2)
    float wc = w - 2.5f;
    float p = -4.39150654e-06f;
    p = fmaf(p, wc, 0.00021858087f);
    p = fmaf(p, wc, -0.00125372503f);
    p = fmaf(p, wc, -0.00417768164f);
    p = fmaf(p, wc, 0.246640727f);
    p = fmaf(p, wc, 1.50140941f);
    float st = mufu_sqrt(w) - 3.0f;
    float pt = fmaf(fmaf(0.00943887047f, st, 1.00167406f), st, 2.83297682f);
    p = (w < 5.0f) ? p : pt;
    return __fmul_rn(p, u);
}

// ---------------- sin(phase): mod-2pi reduction, zero alu ops ----------------
__device__ __forceinline__ float sin_phase(float phase) {
    const float MAGIC = 12582912.0f;                   // 1.5 * 2^23
    const float INV2PI = 0.15915494309189535f;
    const float P1 = 6.28125f;                         // 2pi head, 9 mantissa bits
    const float P2 = 1.9353071795864769e-3f;           // 2pi - P1
    float tmp = fmaf(phase, INV2PI, MAGIC);
    float fk = tmp - MAGIC;                            // exact round-to-nearest integer
    float r = fmaf(fk, -P1, phase);                    // exact
    r = fmaf(fk, -P2, r);                              // one rounding
    return mufu_sin(r);
}

// ---------------- fast tanh ----------------
__device__ __forceinline__ float tanh_fast(float z) {
    float a = fminf(fabsf(z) * 2.8853900817779268f, 64.0f);
    float e = mufu_ex2(a);
    float th = __fmul_rn(e - 1.0f, mufu_rcp(e + 1.0f));
    return copysignf(th, z);
}

// ---------------- Kernel 1: XLA ReduceWindowRewriter radix-16 scan -> g_P2, g_seq8 ----------------
__global__ void scan16_kernel(const float* __restrict__ f0) {
    __shared__ float sm16[TBLK];
    __shared__ float U[TBLK];
    __shared__ float smT1[TBLK * 16];
    __shared__ float inner3[800];
    __shared__ float O2s[800];
    __shared__ float T3[50];
    __shared__ float O3s[50];
    __shared__ float inner4[50];

    const int row = blockIdx.x;                 // 0..143 = b*9+h
    const int b = row / NH, h = row % NH;
    const float m = (float)(h + 1);

    for (int t = threadIdx.x; t < TBLK; t += blockDim.x) {
        float x = __fmul_rn(__fdiv_rn(f0[b * TBLK + t], 48000.0f), m);
        float s = 0.0f;
        g_seq8[(row * TBLK + t) * 8 + 0] = 0.0f;
#pragma unroll
        for (int k = 0; k < 16; k++) {
            s = __fadd_rn(s, x);
            if (k & 1) {                        // k = 2j-1 -> entry j = s_{2j}
                if (k < 15) g_seq8[(row * TBLK + t) * 8 + ((k + 1) >> 1)] = s;
            }
        }
        sm16[t] = s;
    }
    __syncthreads();

    for (int t = threadIdx.x; t < TBLK; t += blockDim.x) {
        float v = sm16[t], s = 0.0f;
#pragma unroll
        for (int k = 0; k < 16; k++) {
            s = __fadd_rn(s, v);
            smT1[t * 16 + k] = s;
        }
        U[t] = s;
    }
    __syncthreads();

    for (int R3 = threadIdx.x; R3 < 50; R3 += blockDim.x) {
        float s = 0.0f;
        for (int j = 0; j < 16; j++) {
            s = __fadd_rn(s, U[(16 * R3 + j) >> 1]);
            inner3[R3 * 16 + j] = s;
        }
        T3[R3] = s;
    }
    __syncthreads();

    if (threadIdx.x == 0) {
        float T4[4], O4[4];
        for (int r = 0; r < 4; r++) {
            float s = 0.0f;
            for (int j = 0; j < 16; j++) {
                int idx = 16 * r + j;
                float v = (idx < 50) ? T3[idx] : 0.0f;
                s = __fadd_rn(s, v);
                if (idx < 50) inner4[idx] = s;
            }
            T4[r] = s;
        }
        float s = 0.0f;
        for (int r = 0; r < 4; r++) { s = __fadd_rn(s, T4[r]); O4[r] = s; }
        for (int i = 0; i < 50; i++) {
            float e = ((i >> 4) == 0) ? 0.0f : O4[(i >> 4) - 1];
            O3s[i] = __fadd_rn(inner4[i], e);
        }
    }
    __syncthreads();

    for (int i2 = threadIdx.x; i2 < 800; i2 += blockDim.x) {
        float e = ((i2 >> 4) == 0) ? 0.0f : O3s[(i2 >> 4) - 1];
        O2s[i2] = __fadd_rn(inner3[i2], e);
    }
    __syncthreads();

    if (threadIdx.x == 0) g_P2[row * (NROW1 + 1)] = 0.0f;
    for (int R = threadIdx.x; R < NROW1; R += blockDim.x) {
        int t = R >> 5, k = R & 15, R2 = R >> 4;
        float e = (R2 == 0) ? 0.0f : O2s[R2 - 1];
        g_P2[row * (NROW1 + 1) + R + 1] = __fadd_rn(smT1[t * 16 + k], e);
    }
}

// ---------------- Kernel 2: one thread = 2 samples (eighth of a radix-16 row) ----------------
__global__ void __launch_bounds__(256) nsf_kernel(const float* __restrict__ f0,
                                                  const float* __restrict__ W,
                                                  const float* __restrict__ bias,
                                                  float* __restrict__ out) {
    const int T = blockIdx.x * blockDim.x + threadIdx.x;   // 0 .. BATCH*TU/2-1
    const int b = T / (TU / SPT);
    const int q = T - b * (TU / SPT);                      // eighth-row index in batch
    const int R = q >> 3;                                  // radix-16 row
    const int qi = q & 7;                                  // which eighth (window pos 2*qi)
    const int t = R >> 5;
    const int s0 = q << 1;                                 // first sample in batch row

    const uint32_t one = g_one;
    const uint32_t nbase = (uint32_t)(b * TU + s0) * (uint32_t)NH;

    const float f0t = __ldg(&f0[b * TBLK + t]);
    const float rad = __fdiv_rn(f0t, 48000.0f);
    const bool voiced = (f0t > 1.0f);
    const float bias0 = __ldg(&bias[0]);
    const float namp2 = voiced ? 0.0042426406871192851f   // 0.003  * sqrt(2)
                               : 0.047140452079103173f;   // 0.1/3  * sqrt(2)
    const float samp  = voiced ? 0.1f : 0.0f;

    float xh[NH], pre[NH], seqv[NH], wv[NH];
#pragma unroll
    for (int h = 0; h < NH; h++) {
        const int row = b * NH + h;
        xh[h]   = __fmul_rn(rad, (float)(h + 1));                 // fl(rad*m): matches scan16
        pre[h]  = __ldg(&g_P2[row * (NROW1 + 1) + R]);            // padded: no select
        seqv[h] = __ldg(&g_seq8[(row * TBLK + t) * 8 + qi]);      // exact chain checkpoint s_{2qi}
        wv[h]   = __ldg(&W[h]);
    }

    float2 o;
    float* ov = &o.x;
#pragma unroll
    for (int i = 0; i < SPT; i++) {
        float accS = 0.0f, accN = 0.0f;
#pragma unroll
        for (int h = 0; h < NH; h++) {
            seqv[h] = __fadd_rn(seqv[h], xh[h]);          // continue exact window chain
            const float C = __fadd_rn(seqv[h], pre[h]);
            const float phase = __fmul_rn(C, 6.283185307179586f);
            const float sv = sin_phase(phase);
            const uint32_t bits = noise_bits(nbase, (uint32_t)(i * NH + h) + 42u, one);
            const float pu = normal_pu(bits);
            accS = fmaf(sv, wv[h], accS);
            accN = fmaf(pu, wv[h], accN);
        }
        float z = fmaf(accN, namp2, bias0);
        z = fmaf(accS, samp, z);
        ov[i] = tanh_fast(z);
    }
    reinterpret_cast<float2*>(out)[T] = o;                 // coalesced 8B store
}

extern "C" void kernel_launch(void* const* d_in, const int* in_sizes, int n_in,
                              void* d_out, int out_size) {
    const float* f0 = (const float*)d_in[0];
    const float* W;
    const float* bias;
    if (n_in >= 4 && in_sizes[2] == NH)      { W = (const float*)d_in[2]; bias = (const float*)d_in[3]; }
    else if (n_in >= 3 && in_sizes[1] == NH) { W = (const float*)d_in[1]; bias = (const float*)d_in[2]; }
    else                                     { W = (const float*)d_in[2]; bias = (const float*)d_in[3]; }
    float* out = (float*)d_out;

    scan16_kernel<<<BATCH * NH, 256>>>(f0);
    const int nthreads = BATCH * TU / SPT;                 // 1638400
    nsf_kernel<<<nthreads / 256, 256>>>(f0, W, bias, out);
}